// round 15
// baseline (speedup 1.0000x reference)
#include <cuda_runtime.h>

#define TT 32
#define PP 16
#define NN 65536
#define HH 128
#define NTHREADS 128
#define NBLOCKS 256   // 256*128 threads; lane-pairs share 4 points -> 65536 pts

#define OFF_ARG (TT * NN * 3)      // 6291456
#define OFF_TL  (OFF_ARG + NN)     // 6356992

__device__ __forceinline__ unsigned long long packrep(float a) {
    unsigned long long r;
    asm("mov.b64 %0, {%1, %1};" : "=l"(r) : "f"(a));
    return r;
}
__device__ __forceinline__ void fma2(unsigned long long& d, unsigned long long a, unsigned long long b) {
    asm("fma.rn.f32x2 %0, %1, %2, %0;" : "+l"(d) : "l"(a), "l"(b));
}
__device__ __forceinline__ void unpack2(unsigned long long v, float& lo, float& hi) {
    asm("mov.b64 {%0, %1}, %2;" : "=f"(lo), "=f"(hi) : "l"(v));
}

__global__ void __launch_bounds__(NTHREADS) fused_kernel(
    const float* __restrict__ cano, const float* __restrict__ w1,
    const float* __restrict__ b1, const float* __restrict__ w2,
    const float* __restrict__ b2, const float* __restrict__ p6d,
    const float* __restrict__ pt, const float* __restrict__ gum,
    float* __restrict__ out)
{
    __shared__ float4 s_w1[HH];                        // w1 row + b1
    __shared__ __align__(16) float4 s_w2[HH][2][2];    // [h][half][j]: experts 8*half+4j..+3
    __shared__ __align__(16) float s_R[TT * PP][12];   // R rows + t

    const int tid = threadIdx.x;

    // ---- stage weights ----
    s_w1[tid] = make_float4(w1[3 * tid], w1[3 * tid + 1], w1[3 * tid + 2], b1[tid]);
    #pragma unroll
    for (int k = 0; k < 4; k++) {           // 512 float4 slots / 128 threads
        int idx = k * NTHREADS + tid;       // 0..511 = h*4 + (half*2+j)
        int h = idx >> 2;
        int hf = (idx >> 1) & 1;
        int j = idx & 1;
        int e0 = 8 * hf + 4 * j;
        s_w2[h][hf][j] = make_float4(w2[(e0 + 0) * HH + h], w2[(e0 + 1) * HH + h],
                                     w2[(e0 + 2) * HH + h], w2[(e0 + 3) * HH + h]);
    }

    // ---- per-block rotation table ----
    #pragma unroll
    for (int k = 0; k < 4; k++) {
        int e = k * NTHREADS + tid;         // 0..511 = t*16+p
        float a1x = p6d[e * 6 + 0], a1y = p6d[e * 6 + 1], a1z = p6d[e * 6 + 2];
        float a2x = p6d[e * 6 + 3], a2y = p6d[e * 6 + 4], a2z = p6d[e * 6 + 5];
        float inv = rsqrtf(a1x * a1x + a1y * a1y + a1z * a1z);
        float b1x = a1x * inv, b1y = a1y * inv, b1z = a1z * inv;
        float d = b1x * a2x + b1y * a2y + b1z * a2z;
        float cx = a2x - d * b1x, cy = a2y - d * b1y, cz = a2z - d * b1z;
        float inv2 = rsqrtf(cx * cx + cy * cy + cz * cz);
        float b2x = cx * inv2, b2y = cy * inv2, b2z = cz * inv2;
        float b3x = b1y * b2z - b1z * b2y;
        float b3y = b1z * b2x - b1x * b2z;
        float b3z = b1x * b2y - b1y * b2x;
        float t0 = pt[e * 3 + 0], t1 = pt[e * 3 + 1], t2 = pt[e * 3 + 2];
        float* r = s_R[e];
        r[0] = b1x; r[1] = b1y; r[2] = b1z;
        r[3] = b2x; r[4] = b2y; r[5] = b2z;
        r[6] = b3x; r[7] = b3y; r[8] = b3z;
        r[9] = t0;  r[10] = t1; r[11] = t2;
        if (blockIdx.x == 0) {
            float* o = out + OFF_TL + e * 16;
            o[0] = b1x; o[1] = b1y; o[2]  = b1z; o[3]  = t0;
            o[4] = b2x; o[5] = b2y; o[6]  = b2z; o[7]  = t1;
            o[8] = b3x; o[9] = b3y; o[10] = b3z; o[11] = t2;
            o[12] = 0.f; o[13] = 0.f; o[14] = 0.f; o[15] = 1.f;
        }
    }

    // ---- lane-pair layout: pair (2k,2k+1) shares 4 points ----
    // half=0 lane: computes h for pts 0,1; owns experts 0-7
    // half=1 lane: computes h for pts 2,3; owns experts 8-15
    const int gtid = blockIdx.x * NTHREADS + tid;
    const int q = gtid >> 1;        // pair id
    const int half = gtid & 1;
    const int n0 = q * 4;

    const float4* c4 = reinterpret_cast<const float4*>(cano + (size_t)n0 * 3);
    float4 ca = c4[0], cb = c4[1], cc = c4[2];
    float px[4], py[4], pz[4];
    px[0] = ca.x; py[0] = ca.y; pz[0] = ca.z;
    px[1] = ca.w; py[1] = cb.x; pz[1] = cb.y;
    px[2] = cb.z; py[2] = cb.w; pz[2] = cc.x;
    px[3] = cc.y; py[3] = cc.z; pz[3] = cc.w;

    // my two MLP points (coords into scalars so the loop body is branch-free)
    const float mxa = px[2 * half],     mya = py[2 * half],     mza = pz[2 * half];
    const float mxb = px[2 * half + 1], myb = py[2 * half + 1], mzb = pz[2 * half + 1];

    // seg slots: [0]=my pt a, [1]=my pt b, [2]=partner pt a, [3]=partner pt b
    unsigned long long seg[4][4];
    {
        const unsigned long long* b2p =
            reinterpret_cast<const unsigned long long*>(b2 + 8 * half);
        unsigned long long bb0 = b2p[0], bb1 = b2p[1], bb2 = b2p[2], bb3 = b2p[3];
        #pragma unroll
        for (int k = 0; k < 4; k++) {
            seg[k][0] = bb0; seg[k][1] = bb1; seg[k][2] = bb2; seg[k][3] = bb3;
        }
    }

    __syncthreads();

    // ---- MLP: 3 LDS.128 + 6 FFMA + 2 shfl + 16 fma2 per iter (4 points) ----
    #pragma unroll 4
    for (int h = 0; h < HH; h++) {
        float4 w = s_w1[h];
        float ha = fmaxf(fmaf(mxa, w.x, fmaf(mya, w.y, fmaf(mza, w.z, w.w))), 0.0f);
        float hb = fmaxf(fmaf(mxb, w.x, fmaf(myb, w.y, fmaf(mzb, w.z, w.w))), 0.0f);
        float ra = __shfl_xor_sync(0xffffffffu, ha, 1);
        float rb = __shfl_xor_sync(0xffffffffu, hb, 1);
        unsigned long long h2[4];
        h2[0] = packrep(ha); h2[1] = packrep(hb);
        h2[2] = packrep(ra); h2[3] = packrep(rb);
        ulonglong2 u0 = *reinterpret_cast<const ulonglong2*>(&s_w2[h][half][0]);
        #pragma unroll
        for (int k = 0; k < 4; k++) {
            fma2(seg[k][0], h2[k], u0.x);
            fma2(seg[k][1], h2[k], u0.y);
        }
        ulonglong2 u1 = *reinterpret_cast<const ulonglong2*>(&s_w2[h][half][1]);
        #pragma unroll
        for (int k = 0; k < 4; k++) {
            fma2(seg[k][2], h2[k], u1.x);
            fma2(seg[k][3], h2[k], u1.y);
        }
    }

    // ---- per-point argmax: local over my 8 experts, point-indexed, pair-combined ----
    float ma_p[4], ia_p[4], ms_p[4], is_p[4];
    #pragma unroll
    for (int k = 0; k < 4; k++) {
        // slot k -> actual point index
        int ptk = (k < 2) ? (2 * half + k) : (2 * (1 - half) + (k - 2));
        float s[8];
        unpack2(seg[k][0], s[0], s[1]);
        unpack2(seg[k][1], s[2], s[3]);
        unpack2(seg[k][2], s[4], s[5]);
        unpack2(seg[k][3], s[6], s[7]);

        int ia = 0; float ma = s[0];
        #pragma unroll
        for (int j = 1; j < 8; j++)
            if (s[j] > ma) { ma = s[j]; ia = j; }

        const float4* g4 =
            reinterpret_cast<const float4*>(gum + (size_t)(n0 + ptk) * PP + 8 * half);
        float4 g0 = g4[0], g1 = g4[1];
        const float gg[8] = { g0.x, g0.y, g0.z, g0.w, g1.x, g1.y, g1.z, g1.w };
        int is = 0; float ms = s[0] + gg[0];
        #pragma unroll
        for (int j = 1; j < 8; j++) {
            float a = s[j] + gg[j];
            if (a > ms) { ms = a; is = j; }
        }
        ma_p[ptk] = ma; ia_p[ptk] = (float)(8 * half + ia);
        ms_p[ptk] = ms; is_p[ptk] = (float)(8 * half + is);
    }

    int sel[4];
    float argm[4];
    #pragma unroll
    for (int p = 0; p < 4; p++) {
        float o_ma = __shfl_xor_sync(0xffffffffu, ma_p[p], 1);
        float o_ia = __shfl_xor_sync(0xffffffffu, ia_p[p], 1);
        float o_ms = __shfl_xor_sync(0xffffffffu, ms_p[p], 1);
        float o_is = __shfl_xor_sync(0xffffffffu, is_p[p], 1);
        float ma = ma_p[p], ia = ia_p[p], ms = ms_p[p], is = is_p[p];
        if (o_ma > ma || (o_ma == ma && o_ia < ia)) { ma = o_ma; ia = o_ia; }
        if (o_ms > ms || (o_ms == ms && o_is < is)) { ms = o_ms; is = o_is; }
        argm[p] = ia;
        sel[p] = (int)is;
    }

    if (half == 0)
        *reinterpret_cast<float4*>(out + OFF_ARG + n0) =
            make_float4(argm[0], argm[1], argm[2], argm[3]);

    // ---- epilogue: pair splits t 16/16; 3 STG.128 per t (16q-aligned) ----
    #pragma unroll 2
    for (int tt = 0; tt < 16; tt++) {
        const int t = half * 16 + tt;
        float o[4][3];
        #pragma unroll
        for (int k = 0; k < 4; k++) {
            const float4* R = reinterpret_cast<const float4*>(s_R[t * PP + sel[k]]);
            float4 r0 = R[0], r1 = R[1], r2 = R[2];
            o[k][0] = fmaf(px[k], r0.x, fmaf(py[k], r0.y, fmaf(pz[k], r0.z, r2.y)));
            o[k][1] = fmaf(px[k], r0.w, fmaf(py[k], r1.x, fmaf(pz[k], r1.y, r2.z)));
            o[k][2] = fmaf(px[k], r1.z, fmaf(py[k], r1.w, fmaf(pz[k], r2.x, r2.w)));
        }
        float4* dst = reinterpret_cast<float4*>(out + (size_t)(t * NN + n0) * 3);
        dst[0] = make_float4(o[0][0], o[0][1], o[0][2], o[1][0]);
        dst[1] = make_float4(o[1][1], o[1][2], o[2][0], o[2][1]);
        dst[2] = make_float4(o[2][2], o[3][0], o[3][1], o[3][2]);
    }
}

extern "C" void kernel_launch(void* const* d_in, const int* in_sizes, int n_in,
                              void* d_out, int out_size) {
    (void)in_sizes; (void)n_in; (void)out_size;
    fused_kernel<<<NBLOCKS, NTHREADS>>>(
        (const float*)d_in[0],  // cano_pc
        (const float*)d_in[1],  // w1
        (const float*)d_in[2],  // b1
        (const float*)d_in[3],  // w2
        (const float*)d_in[4],  // b2
        (const float*)d_in[5],  // proposal_6d
        (const float*)d_in[6],  // proposal_t
        (const float*)d_in[7],  // gumbel
        (float*)d_out);
}

// round 16
// speedup vs baseline: 1.1913x; 1.1913x over previous
#include <cuda_runtime.h>

#define TT 32
#define PP 16
#define NN 65536
#define HH 128
#define NTHREADS 128
#define NBLOCKS 256   // 256 blocks * 128 threads * 2 points = 65536

#define OFF_ARG (TT * NN * 3)      // 6291456
#define OFF_TL  (OFF_ARG + NN)     // 6356992

__global__ void __launch_bounds__(NTHREADS) fused_kernel(
    const float* __restrict__ cano, const float* __restrict__ w1,
    const float* __restrict__ b1, const float* __restrict__ w2,
    const float* __restrict__ b2, const float* __restrict__ p6d,
    const float* __restrict__ pt, const float* __restrict__ gum,
    float* __restrict__ out)
{
    __shared__ float4 s_w1[HH];                        // w1 row + b1
    __shared__ __align__(16) float4 s_w2[HH][4];       // [h][j] = w2 experts 4j..4j+3 at h
    __shared__ __align__(16) float s_R[TT * PP][12];   // R rows + t

    const int tid = threadIdx.x;

    // ---- stage weights into shared memory ----
    s_w1[tid] = make_float4(w1[3 * tid], w1[3 * tid + 1], w1[3 * tid + 2], b1[tid]);
    #pragma unroll
    for (int k = 0; k < 4; k++)
        s_w2[tid][k] = make_float4(w2[(4 * k + 0) * HH + tid], w2[(4 * k + 1) * HH + tid],
                                   w2[(4 * k + 2) * HH + tid], w2[(4 * k + 3) * HH + tid]);

    // ---- per-block rotation table ----
    #pragma unroll
    for (int k = 0; k < 4; k++) {
        int e = k * NTHREADS + tid;       // 0..511 = t*16+p
        float a1x = p6d[e * 6 + 0], a1y = p6d[e * 6 + 1], a1z = p6d[e * 6 + 2];
        float a2x = p6d[e * 6 + 3], a2y = p6d[e * 6 + 4], a2z = p6d[e * 6 + 5];
        float inv = rsqrtf(a1x * a1x + a1y * a1y + a1z * a1z);
        float b1x = a1x * inv, b1y = a1y * inv, b1z = a1z * inv;
        float d = b1x * a2x + b1y * a2y + b1z * a2z;
        float cx = a2x - d * b1x, cy = a2y - d * b1y, cz = a2z - d * b1z;
        float inv2 = rsqrtf(cx * cx + cy * cy + cz * cz);
        float b2x = cx * inv2, b2y = cy * inv2, b2z = cz * inv2;
        float b3x = b1y * b2z - b1z * b2y;
        float b3y = b1z * b2x - b1x * b2z;
        float b3z = b1x * b2y - b1y * b2x;
        float t0 = pt[e * 3 + 0], t1 = pt[e * 3 + 1], t2 = pt[e * 3 + 2];
        float* r = s_R[e];
        r[0] = b1x; r[1] = b1y; r[2] = b1z;
        r[3] = b2x; r[4] = b2y; r[5] = b2z;
        r[6] = b3x; r[7] = b3y; r[8] = b3z;
        r[9] = t0;  r[10] = t1; r[11] = t2;
        if (blockIdx.x == 0) {
            float* o = out + OFF_TL + e * 16;
            o[0] = b1x; o[1] = b1y; o[2]  = b1z; o[3]  = t0;
            o[4] = b2x; o[5] = b2y; o[6]  = b2z; o[7]  = t1;
            o[8] = b3x; o[9] = b3y; o[10] = b3z; o[11] = t2;
            o[12] = 0.f; o[13] = 0.f; o[14] = 0.f; o[15] = 1.f;
        }
    }

    const int i = blockIdx.x * NTHREADS + tid;
    const int nA = 2 * i;

    // cano: 24*i bytes -> 8-aligned: float2 loads
    const float2* c2 = reinterpret_cast<const float2*>(cano + (size_t)nA * 3);
    float2 ca = c2[0], cb = c2[1], cc = c2[2];
    const float xAx = ca.x, xAy = ca.y, xAz = cb.x;
    const float xBx = cb.y, xBy = cc.x, xBz = cc.y;

    // gumbel prefetch (16-aligned)
    const float4* g4 = reinterpret_cast<const float4*>(gum + (size_t)nA * PP);
    float4 gA0 = g4[0], gA1 = g4[1], gA2 = g4[2], gA3 = g4[3];
    float4 gB0 = g4[4], gB1 = g4[5], gB2 = g4[6], gB3 = g4[7];

    // plain scalar accumulators — NO inline asm anywhere in the hot loop
    float sA[16], sB[16];
    #pragma unroll
    for (int k = 0; k < 4; k++) {
        float4 bb = reinterpret_cast<const float4*>(b2)[k];
        sA[4 * k + 0] = bb.x; sA[4 * k + 1] = bb.y; sA[4 * k + 2] = bb.z; sA[4 * k + 3] = bb.w;
        sB[4 * k + 0] = bb.x; sB[4 * k + 1] = bb.y; sB[4 * k + 2] = bb.z; sB[4 * k + 3] = bb.w;
    }

    __syncthreads();

    // ---- MLP: pure C, ptxas schedules freely ----
    #pragma unroll 4
    for (int h = 0; h < HH; h++) {
        float4 w = s_w1[h];
        float hA = fmaxf(fmaf(xAx, w.x, fmaf(xAy, w.y, fmaf(xAz, w.z, w.w))), 0.0f);
        float hB = fmaxf(fmaf(xBx, w.x, fmaf(xBy, w.y, fmaf(xBz, w.z, w.w))), 0.0f);
        #pragma unroll
        for (int k = 0; k < 4; k++) {
            float4 q = s_w2[h][k];
            sA[4 * k + 0] = fmaf(hA, q.x, sA[4 * k + 0]);
            sA[4 * k + 1] = fmaf(hA, q.y, sA[4 * k + 1]);
            sA[4 * k + 2] = fmaf(hA, q.z, sA[4 * k + 2]);
            sA[4 * k + 3] = fmaf(hA, q.w, sA[4 * k + 3]);
            sB[4 * k + 0] = fmaf(hB, q.x, sB[4 * k + 0]);
            sB[4 * k + 1] = fmaf(hB, q.y, sB[4 * k + 1]);
            sB[4 * k + 2] = fmaf(hB, q.z, sB[4 * k + 2]);
            sB[4 * k + 3] = fmaf(hB, q.w, sB[4 * k + 3]);
        }
    }

    // argmax(seg) — first-occurrence semantics
    int iaA = 0, iaB = 0;
    float mA = sA[0], mB = sB[0];
    #pragma unroll
    for (int p = 1; p < PP; p++) {
        if (sA[p] > mA) { mA = sA[p]; iaA = p; }
        if (sB[p] > mB) { mB = sB[p]; iaB = p; }
    }
    reinterpret_cast<float2*>(out + OFF_ARG + nA)[0] = make_float2((float)iaA, (float)iaB);

    // selection = argmax(seg + gumbel)
    const float ggA[16] = { gA0.x, gA0.y, gA0.z, gA0.w, gA1.x, gA1.y, gA1.z, gA1.w,
                            gA2.x, gA2.y, gA2.z, gA2.w, gA3.x, gA3.y, gA3.z, gA3.w };
    const float ggB[16] = { gB0.x, gB0.y, gB0.z, gB0.w, gB1.x, gB1.y, gB1.z, gB1.w,
                            gB2.x, gB2.y, gB2.z, gB2.w, gB3.x, gB3.y, gB3.z, gB3.w };
    int selA = 0, selB = 0;
    float vmA = -1e30f, vmB = -1e30f;
    #pragma unroll
    for (int q = 0; q < PP; q++) {
        float a = sA[q] + ggA[q];
        float b = sB[q] + ggB[q];
        if (a > vmA) { vmA = a; selA = q; }
        if (b > vmB) { vmB = b; selB = q; }
    }

    // epilogue: pc_out[t,n,:] = R[t,sel] @ x + t[t,sel]  (float2 stores: 8-aligned)
    #pragma unroll 4
    for (int t = 0; t < TT; t++) {
        const float4* RA = reinterpret_cast<const float4*>(s_R[t * PP + selA]);
        float4 a0 = RA[0], a1 = RA[1], a2 = RA[2];
        float oA0 = fmaf(xAx, a0.x, fmaf(xAy, a0.y, fmaf(xAz, a0.z, a2.y)));
        float oA1 = fmaf(xAx, a0.w, fmaf(xAy, a1.x, fmaf(xAz, a1.y, a2.z)));
        float oA2 = fmaf(xAx, a1.z, fmaf(xAy, a1.w, fmaf(xAz, a2.x, a2.w)));
        const float4* RB = reinterpret_cast<const float4*>(s_R[t * PP + selB]);
        float4 c0 = RB[0], c1 = RB[1], c2 = RB[2];
        float oB0 = fmaf(xBx, c0.x, fmaf(xBy, c0.y, fmaf(xBz, c0.z, c2.y)));
        float oB1 = fmaf(xBx, c0.w, fmaf(xBy, c1.x, fmaf(xBz, c1.y, c2.z)));
        float oB2 = fmaf(xBx, c1.z, fmaf(xBy, c1.w, fmaf(xBz, c2.x, c2.w)));
        float2* dst = reinterpret_cast<float2*>(out + (size_t)(t * NN + nA) * 3);
        dst[0] = make_float2(oA0, oA1);
        dst[1] = make_float2(oA2, oB0);
        dst[2] = make_float2(oB1, oB2);
    }
}

extern "C" void kernel_launch(void* const* d_in, const int* in_sizes, int n_in,
                              void* d_out, int out_size) {
    (void)in_sizes; (void)n_in; (void)out_size;
    fused_kernel<<<NBLOCKS, NTHREADS>>>(
        (const float*)d_in[0],  // cano_pc
        (const float*)d_in[1],  // w1
        (const float*)d_in[2],  // b1
        (const float*)d_in[3],  // w2
        (const float*)d_in[4],  // b2
        (const float*)d_in[5],  // proposal_6d
        (const float*)d_in[6],  // proposal_t
        (const float*)d_in[7],  // gumbel
        (float*)d_out);
}

// round 17
// speedup vs baseline: 1.2470x; 1.0467x over previous
#include <cuda_runtime.h>
#include <cstdint>

#define TT 32
#define PP 16
#define NN 65536
#define HH 128
#define NTHREADS 128
#define NBLOCKS 512            // 512 CTAs * 128 points

#define OFF_ARG (TT * NN * 3)  // 6291456
#define OFF_TL  (OFF_ARG + NN) // 6356992

// dynamic smem layout (bytes); A rows: 64 k + 4 pad = 68 floats (bank-conflict-free frags)
#define SM_A    0                         // h tile: 128 pts x 68 floats = 34816 B (per k-pass)
#define SM_W2   34816                     // w2^T: 128 k x 17 floats = 8704 B
#define SM_R    43520                     // R table: 512*12 floats = 24576 B
#define SM_W1   68096                     // w1+b1: 128 float4 = 2048 B
#define SM_SEL  70144                     // 128 ints
#define SM_TOT  70656

__device__ __forceinline__ float tf32_hi(float v) {
    return __uint_as_float(__float_as_uint(v) & 0xFFFFE000u);
}
__device__ __forceinline__ void mma_tf32(float* c, const float* a2, const float* b2v) {
    asm volatile(
        "mma.sync.aligned.m16n8k8.row.col.f32.tf32.tf32.f32 "
        "{%0,%1,%2,%3}, {%4,%5,%6,%7}, {%8,%9}, {%0,%1,%2,%3};"
        : "+f"(c[0]), "+f"(c[1]), "+f"(c[2]), "+f"(c[3])
        : "r"(__float_as_uint(a2[0])), "r"(__float_as_uint(a2[1])),
          "r"(__float_as_uint(a2[2])), "r"(__float_as_uint(a2[3])),
          "r"(__float_as_uint(b2v[0])), "r"(__float_as_uint(b2v[1])));
}

__global__ void __launch_bounds__(NTHREADS) fused_kernel(
    const float* __restrict__ cano, const float* __restrict__ w1,
    const float* __restrict__ b1, const float* __restrict__ w2,
    const float* __restrict__ b2, const float* __restrict__ p6d,
    const float* __restrict__ pt, const float* __restrict__ gum,
    float* __restrict__ out)
{
    extern __shared__ __align__(16) char smem[];
    float* sA  = reinterpret_cast<float*>(smem + SM_A);
    float* sW2 = reinterpret_cast<float*>(smem + SM_W2);
    float* sR  = reinterpret_cast<float*>(smem + SM_R);
    float4* sW1 = reinterpret_cast<float4*>(smem + SM_W1);
    int* sSel = reinterpret_cast<int*>(smem + SM_SEL);

    const int tid = threadIdx.x;
    const int wid = tid >> 5;
    const int lane = tid & 31;
    const int lg = lane >> 2;      // group row 0..7
    const int lc = lane & 3;       // group col 0..3

    // ---- stage w1+b1 ----
    sW1[tid] = make_float4(w1[3 * tid], w1[3 * tid + 1], w1[3 * tid + 2], b1[tid]);

    // ---- stage w2^T: sW2[k*17 + e] = w2[e][k] ----
    #pragma unroll
    for (int e = 0; e < PP; e++)
        sW2[tid * 17 + e] = w2[e * HH + tid];

    // ---- R table (+ trans_list from block 0) ----
    #pragma unroll
    for (int k = 0; k < 4; k++) {
        int e = k * NTHREADS + tid;
        float a1x = p6d[e * 6 + 0], a1y = p6d[e * 6 + 1], a1z = p6d[e * 6 + 2];
        float a2x = p6d[e * 6 + 3], a2y = p6d[e * 6 + 4], a2z = p6d[e * 6 + 5];
        float inv = rsqrtf(a1x * a1x + a1y * a1y + a1z * a1z);
        float b1x = a1x * inv, b1y = a1y * inv, b1z = a1z * inv;
        float d = b1x * a2x + b1y * a2y + b1z * a2z;
        float cx = a2x - d * b1x, cy = a2y - d * b1y, cz = a2z - d * b1z;
        float inv2 = rsqrtf(cx * cx + cy * cy + cz * cz);
        float b2x = cx * inv2, b2y = cy * inv2, b2z = cz * inv2;
        float b3x = b1y * b2z - b1z * b2y;
        float b3y = b1z * b2x - b1x * b2z;
        float b3z = b1x * b2y - b1y * b2x;
        float t0 = pt[e * 3 + 0], t1 = pt[e * 3 + 1], t2 = pt[e * 3 + 2];
        float* r = sR + e * 12;
        r[0] = b1x; r[1] = b1y; r[2] = b1z;
        r[3] = b2x; r[4] = b2y; r[5] = b2z;
        r[6] = b3x; r[7] = b3y; r[8] = b3z;
        r[9] = t0;  r[10] = t1; r[11] = t2;
        if (blockIdx.x == 0) {
            float* o = out + OFF_TL + e * 16;
            o[0] = b1x; o[1] = b1y; o[2]  = b1z; o[3]  = t0;
            o[4] = b2x; o[5] = b2y; o[6]  = b2z; o[7]  = t1;
            o[8] = b3x; o[9] = b3y; o[10] = b3z; o[11] = t2;
            o[12] = 0.f; o[13] = 0.f; o[14] = 0.f; o[15] = 1.f;
        }
    }

    // my point
    const int ptg = blockIdx.x * NTHREADS + tid;
    const float mx = cano[3 * ptg], my = cano[3 * ptg + 1], mz = cano[3 * ptg + 2];

    __syncthreads();   // staging done (covers w1/w2/R for all phases)

    const int m0w = wid * 32;   // this warp's 32 CTA-local points

    // C fragments: [mtile][ntile][4]
    float c[2][2][4];
    #pragma unroll
    for (int a = 0; a < 2; a++)
        #pragma unroll
        for (int b = 0; b < 2; b++)
            #pragma unroll
            for (int j = 0; j < 4; j++) c[a][b][j] = 0.0f;

    // ---- two k-passes: layer1 into warp-local A tile, then 8 k-tiles of MMA ----
    #pragma unroll
    for (int pass = 0; pass < 2; pass++) {
        // layer1: 64 h values for my point -> sA[tid][0..63]
        #pragma unroll 4
        for (int kk = 0; kk < 16; kk++) {
            int h0 = pass * 64 + kk * 4;
            float hv[4];
            #pragma unroll
            for (int j = 0; j < 4; j++) {
                float4 w = sW1[h0 + j];
                hv[j] = fmaxf(fmaf(mx, w.x, fmaf(my, w.y, fmaf(mz, w.z, w.w))), 0.0f);
            }
            *reinterpret_cast<float4*>(sA + tid * 68 + kk * 4) =
                make_float4(hv[0], hv[1], hv[2], hv[3]);
        }
        __syncwarp();

        // MMA over this pass's 8 k-tiles
        #pragma unroll
        for (int kt = 0; kt < 8; kt++) {
            int k0g = pass * 64 + kt * 8;   // global k for B
            int k0l = kt * 8;               // local k within A tile
            // B fragments (2 n-tiles), hi/lo
            float bh[2][2], bl[2][2];
            #pragma unroll
            for (int nt = 0; nt < 2; nt++) {
                float v0 = sW2[(k0g + lc) * 17 + nt * 8 + lg];
                float v1 = sW2[(k0g + lc + 4) * 17 + nt * 8 + lg];
                bh[nt][0] = tf32_hi(v0); bl[nt][0] = v0 - bh[nt][0];
                bh[nt][1] = tf32_hi(v1); bl[nt][1] = v1 - bh[nt][1];
            }
            #pragma unroll
            for (int mt = 0; mt < 2; mt++) {
                int mb = m0w + mt * 16;
                float a0 = sA[(mb + lg) * 68 + k0l + lc];
                float a1 = sA[(mb + lg + 8) * 68 + k0l + lc];
                float a2v = sA[(mb + lg) * 68 + k0l + lc + 4];
                float a3 = sA[(mb + lg + 8) * 68 + k0l + lc + 4];
                float ah[4] = { tf32_hi(a0), tf32_hi(a1), tf32_hi(a2v), tf32_hi(a3) };
                float al[4] = { a0 - ah[0], a1 - ah[1], a2v - ah[2], a3 - ah[3] };
                #pragma unroll
                for (int nt = 0; nt < 2; nt++) {
                    mma_tf32(c[mt][nt], ah, bh[nt]);
                    mma_tf32(c[mt][nt], ah, bl[nt]);
                    mma_tf32(c[mt][nt], al, bh[nt]);
                }
            }
        }
        __syncwarp();
    }

    // ---- bias ----
    #pragma unroll
    for (int nt = 0; nt < 2; nt++) {
        float be0 = b2[nt * 8 + 2 * lc];
        float be1 = b2[nt * 8 + 2 * lc + 1];
        #pragma unroll
        for (int mt = 0; mt < 2; mt++) {
            c[mt][nt][0] += be0; c[mt][nt][1] += be1;
            c[mt][nt][2] += be0; c[mt][nt][3] += be1;
        }
    }

    // ---- per-point argmax (4 pts per lane), combined across the 4-lane group ----
    #pragma unroll
    for (int mt = 0; mt < 2; mt++) {
        #pragma unroll
        for (int rh = 0; rh < 2; rh++) {
            int ptl = m0w + mt * 16 + rh * 8 + lg;      // CTA-local point
            int pg  = blockIdx.x * NTHREADS + ptl;      // global point
            // my 4 experts (ascending): 2lc, 2lc+1, 8+2lc, 8+2lc+1
            float v0 = c[mt][0][rh * 2], v1 = c[mt][0][rh * 2 + 1];
            float v2 = c[mt][1][rh * 2], v3 = c[mt][1][rh * 2 + 1];

            // local argmax of seg
            float ma = v0; int ea = 2 * lc;
            if (v1 > ma) { ma = v1; ea = 2 * lc + 1; }
            if (v2 > ma) { ma = v2; ea = 8 + 2 * lc; }
            if (v3 > ma) { ma = v3; ea = 8 + 2 * lc + 1; }

            // local argmax of seg + gumbel
            float2 g0 = *reinterpret_cast<const float2*>(gum + (size_t)pg * PP + 2 * lc);
            float2 g1 = *reinterpret_cast<const float2*>(gum + (size_t)pg * PP + 8 + 2 * lc);
            float s0 = v0 + g0.x, s1 = v1 + g0.y, s2 = v2 + g1.x, s3 = v3 + g1.y;
            float ms = s0; int es = 2 * lc;
            if (s1 > ms) { ms = s1; es = 2 * lc + 1; }
            if (s2 > ms) { ms = s2; es = 8 + 2 * lc; }
            if (s3 > ms) { ms = s3; es = 8 + 2 * lc + 1; }

            // butterfly over lanes lc^1, lc^2 (same point); tie -> lower index
            #pragma unroll
            for (int d = 1; d <= 2; d <<= 1) {
                float o_ma = __shfl_xor_sync(0xffffffffu, ma, d);
                int   o_ea = __shfl_xor_sync(0xffffffffu, ea, d);
                float o_ms = __shfl_xor_sync(0xffffffffu, ms, d);
                int   o_es = __shfl_xor_sync(0xffffffffu, es, d);
                if (o_ma > ma || (o_ma == ma && o_ea < ea)) { ma = o_ma; ea = o_ea; }
                if (o_ms > ms || (o_ms == ms && o_es < es)) { ms = o_ms; es = o_es; }
            }
            if (lc == 0) {
                sSel[ptl] = es;
                out[OFF_ARG + pg] = (float)ea;
            }
        }
    }
    __syncwarp();

    // ---- epilogue: thread t owns point t (same warp wrote sSel[t]) ----
    const int sel = sSel[tid];
    #pragma unroll 4
    for (int t = 0; t < TT; t++) {
        const float4* R = reinterpret_cast<const float4*>(sR + (t * PP + sel) * 12);
        float4 r0 = R[0], r1 = R[1], r2 = R[2];
        float o0 = fmaf(mx, r0.x, fmaf(my, r0.y, fmaf(mz, r0.z, r2.y)));
        float o1 = fmaf(mx, r0.w, fmaf(my, r1.x, fmaf(mz, r1.y, r2.z)));
        float o2 = fmaf(mx, r1.z, fmaf(my, r1.w, fmaf(mz, r2.x, r2.w)));
        float* dst = out + (size_t)(t * NN + ptg) * 3;
        dst[0] = o0;
        dst[1] = o1;
        dst[2] = o2;
    }
}

extern "C" void kernel_launch(void* const* d_in, const int* in_sizes, int n_in,
                              void* d_out, int out_size) {
    (void)in_sizes; (void)n_in; (void)out_size;
    cudaFuncSetAttribute(fused_kernel, cudaFuncAttributeMaxDynamicSharedMemorySize, SM_TOT);
    fused_kernel<<<NBLOCKS, NTHREADS, SM_TOT>>>(
        (const float*)d_in[0],  // cano_pc
        (const float*)d_in[1],  // w1
        (const float*)d_in[2],  // b1
        (const float*)d_in[3],  // w2
        (const float*)d_in[4],  // b2
        (const float*)d_in[5],  // proposal_6d
        (const float*)d_in[6],  // proposal_t
        (const float*)d_in[7],  // gumbel
        (float*)d_out);
}